// round 16
// baseline (speedup 1.0000x reference)
#include <cuda_runtime.h>
#include <cuda_fp16.h>
#include <cstdint>

#define N_NODES 100000
#define N_EDGES 800000
#define D 128
#define NTOT (3 * N_NODES)
#define ETOT (3 * N_EDGES)
#define EQTOT (ETOT / 4)
#define EQ_PER_G (N_EDGES / 4)
#define SCAN_BLK 1024
#define SCAN_NB ((NTOT + SCAN_BLK - 1) / SCAN_BLK)   // 293

// Scratch (device globals — allocation-free rule)
__device__ __half g_xh[3 * N_NODES * D];    // x in fp16
__device__ __half g_aggh[3 * N_NODES * D];  // mean-aggregated messages, fp16
__device__ __half g_h[3 * N_NODES * D];     // layer-1 activations, fp16
__device__ int    g_is64;
// fp16 weights: [layer][g][chunk8][n=128][kc=32]
__device__ __half g_Wh[2 * 3 * 8 * 128 * 32];

// CSR scratch
__device__ int g_cnt[NTOT];
__device__ int g_rowptr[NTOT + 1];
__device__ int g_cursor[NTOT];
__device__ int g_col[ETOT];
__device__ int g_bsum[SCAN_NB];

// ---------------------------------------------------------------------------
__global__ void detect_idx_kernel(const int* __restrict__ ei_words) {
    if (threadIdx.x == 0 && blockIdx.x == 0) {
        int bad = 0;
        #pragma unroll
        for (int i = 0; i < 64; ++i) bad |= ei_words[2 * i + 1];
        g_is64 = (bad == 0) ? 1 : 0;
    }
}

// ---------------------------------------------------------------------------
// CSR build: count -> scan -> fill.  4 edges per thread.
// ---------------------------------------------------------------------------
__device__ __forceinline__ void load_dst4(const void* ei_raw, int g, int e4, int* d) {
    if (g_is64) {
        const long long* ei = (const long long*)ei_raw
            + (long long)g * 2 * N_EDGES + N_EDGES + e4;
        longlong2 a = *(const longlong2*)ei;
        longlong2 b = *(const longlong2*)(ei + 2);
        d[0] = (int)a.x; d[1] = (int)a.y; d[2] = (int)b.x; d[3] = (int)b.y;
    } else {
        const int* ei = (const int*)ei_raw
            + (long long)g * 2 * N_EDGES + N_EDGES + e4;
        int4 v = *(const int4*)ei;
        d[0] = v.x; d[1] = v.y; d[2] = v.z; d[3] = v.w;
    }
}

__device__ __forceinline__ void load_src4(const void* ei_raw, int g, int e4, int* s) {
    if (g_is64) {
        const long long* ei = (const long long*)ei_raw
            + (long long)g * 2 * N_EDGES + e4;
        longlong2 a = *(const longlong2*)ei;
        longlong2 b = *(const longlong2*)(ei + 2);
        s[0] = (int)a.x; s[1] = (int)a.y; s[2] = (int)b.x; s[3] = (int)b.y;
    } else {
        const int* ei = (const int*)ei_raw
            + (long long)g * 2 * N_EDGES + e4;
        int4 v = *(const int4*)ei;
        s[0] = v.x; s[1] = v.y; s[2] = v.z; s[3] = v.w;
    }
}

__global__ void count_kernel(const void* __restrict__ ei_raw) {
    int i = blockIdx.x * blockDim.x + threadIdx.x;
    if (i >= EQTOT) return;
    int g  = i / EQ_PER_G;
    int e4 = (i - g * EQ_PER_G) * 4;
    int d[4];
    load_dst4(ei_raw, g, e4, d);
    #pragma unroll
    for (int j = 0; j < 4; ++j)
        atomicAdd(&g_cnt[g * N_NODES + d[j]], 1);
}

__global__ void scan1_kernel() {
    __shared__ int s[SCAN_BLK];
    int idx = blockIdx.x * SCAN_BLK + threadIdx.x;
    int v = (idx < NTOT) ? g_cnt[idx] : 0;
    s[threadIdx.x] = v;
    __syncthreads();
    #pragma unroll
    for (int off = 1; off < SCAN_BLK; off <<= 1) {
        int t = (threadIdx.x >= off) ? s[threadIdx.x - off] : 0;
        __syncthreads();
        s[threadIdx.x] += t;
        __syncthreads();
    }
    if (idx < NTOT) g_rowptr[idx] = s[threadIdx.x] - v;
    if (threadIdx.x == SCAN_BLK - 1) g_bsum[blockIdx.x] = s[SCAN_BLK - 1];
}

__global__ void scan2_kernel() {
    __shared__ int s[512];
    int v = (threadIdx.x < SCAN_NB) ? g_bsum[threadIdx.x] : 0;
    s[threadIdx.x] = v;
    __syncthreads();
    #pragma unroll
    for (int off = 1; off < 512; off <<= 1) {
        int t = (threadIdx.x >= off) ? s[threadIdx.x - off] : 0;
        __syncthreads();
        s[threadIdx.x] += t;
        __syncthreads();
    }
    if (threadIdx.x < SCAN_NB) g_bsum[threadIdx.x] = s[threadIdx.x] - v;
}

__global__ void scan3_kernel() {
    int idx = blockIdx.x * SCAN_BLK + threadIdx.x;
    if (idx < NTOT) {
        int r = g_rowptr[idx] + g_bsum[blockIdx.x];
        g_rowptr[idx] = r;
        g_cursor[idx] = r;
    }
    if (idx == 0) g_rowptr[NTOT] = ETOT;
}

__global__ void fill_kernel(const void* __restrict__ ei_raw) {
    int i = blockIdx.x * blockDim.x + threadIdx.x;
    if (i >= EQTOT) return;
    int g  = i / EQ_PER_G;
    int e4 = (i - g * EQ_PER_G) * 4;
    int s[4], d[4];
    load_src4(ei_raw, g, e4, s);
    load_dst4(ei_raw, g, e4, d);
    #pragma unroll
    for (int j = 0; j < 4; ++j) {
        int pos = atomicAdd(&g_cursor[g * N_NODES + d[j]], 1);
        g_col[pos] = s[j];
    }
}

// ---------------------------------------------------------------------------
// x -> fp16 preconvert
// ---------------------------------------------------------------------------
__global__ void xh_kernel(const float* __restrict__ X) {
    long long i = (long long)blockIdx.x * blockDim.x + threadIdx.x;
    const long long nv = (long long)NTOT * D / 4;
    if (i >= nv) return;
    float4 v = ((const float4*)X)[i];
    __half2 h0 = __floats2half2_rn(v.x, v.y);
    __half2 h1 = __floats2half2_rn(v.z, v.w);
    uint2 o;
    o.x = *(unsigned*)&h0;
    o.y = *(unsigned*)&h1;
    ((uint2*)g_xh)[i] = o;
}

// Weight preconvert: g_Wh[((lg*8+chunk)*128+n)*32+kc] = fp16(W[k][n]), k=chunk*32+kc
__global__ void wconv_kernel(const float* __restrict__ Wl1, const float* __restrict__ Wr1,
                             const float* __restrict__ Wl2, const float* __restrict__ Wr2) {
    int i = blockIdx.x * blockDim.x + threadIdx.x;   // < 2*3*8*128*32 = 196608
    int lg    = i >> 15;           // layer*3+g
    int rem   = i & 32767;
    int chunk = rem >> 12;
    int n     = (rem >> 5) & 127;
    int kc    = rem & 31;
    int layer = lg / 3, g = lg % 3;
    int k = chunk * 32 + kc;
    const float* Wl = layer ? Wl2 : Wl1;
    const float* Wr = layer ? Wr2 : Wr1;
    float v = (k < 128) ? Wl[(g * 128 + k) * 128 + n]
                        : Wr[(g * 128 + (k - 128)) * 128 + n];
    g_Wh[i] = __float2half_rn(v);
}

// ---------------------------------------------------------------------------
// Gather aggregation (CSR, no atomics). fp16 input -> fp16 agg (both layers).
// ---------------------------------------------------------------------------
__global__ void __launch_bounds__(256)
gather_f16_kernel(const __half* __restrict__ X, __half* __restrict__ agg) {
    int widx = blockIdx.x * (blockDim.x >> 5) + (threadIdx.x >> 5);
    int lane = threadIdx.x & 31;
    if (widx >= NTOT) return;

    int g = widx / N_NODES;
    const uint2* xg = (const uint2*)(X + (size_t)g * N_NODES * D);

    int start = g_rowptr[widx];
    int end   = g_rowptr[widx + 1];

    float4 acc0 = make_float4(0.f, 0.f, 0.f, 0.f);
    float4 acc1 = make_float4(0.f, 0.f, 0.f, 0.f);
    int p = start;
    for (; p + 1 < end; p += 2) {
        int s0 = g_col[p], s1 = g_col[p + 1];
        uint2 v0 = xg[(size_t)s0 * 32 + lane];
        uint2 v1 = xg[(size_t)s1 * 32 + lane];
        float2 f0 = __half22float2(*(__half2*)&v0.x);
        float2 f1 = __half22float2(*(__half2*)&v0.y);
        acc0.x += f0.x; acc0.y += f0.y; acc0.z += f1.x; acc0.w += f1.y;
        float2 f2 = __half22float2(*(__half2*)&v1.x);
        float2 f3 = __half22float2(*(__half2*)&v1.y);
        acc1.x += f2.x; acc1.y += f2.y; acc1.z += f3.x; acc1.w += f3.y;
    }
    if (p < end) {
        int s0 = g_col[p];
        uint2 v0 = xg[(size_t)s0 * 32 + lane];
        float2 f0 = __half22float2(*(__half2*)&v0.x);
        float2 f1 = __half22float2(*(__half2*)&v0.y);
        acc0.x += f0.x; acc0.y += f0.y; acc0.z += f1.x; acc0.w += f1.y;
    }
    acc0.x += acc1.x; acc0.y += acc1.y; acc0.z += acc1.z; acc0.w += acc1.w;

    int deg = end - start;
    float norm = 1.0f / (float)max(deg, 1);
    __half2 h0 = __floats2half2_rn(acc0.x * norm, acc0.y * norm);
    __half2 h1 = __floats2half2_rn(acc0.z * norm, acc0.w * norm);
    uint2 o;
    o.x = *(unsigned*)&h0;
    o.y = *(unsigned*)&h1;
    ((uint2*)agg)[(size_t)widx * 32 + lane] = o;
}

// ---------------------------------------------------------------------------
// cp.async helpers
// ---------------------------------------------------------------------------
__device__ __forceinline__ void cp_async16z(uint32_t dst, const void* src, int bytes) {
    asm volatile("cp.async.cg.shared.global [%0], [%1], 16, %2;"
                 :: "r"(dst), "l"(src), "r"(bytes));
}
__device__ __forceinline__ void cp_async16(uint32_t dst, const void* src) {
    asm volatile("cp.async.cg.shared.global [%0], [%1], 16;"
                 :: "r"(dst), "l"(src));
}
__device__ __forceinline__ void cp_commit() {
    asm volatile("cp.async.commit_group;");
}
template <int N>
__device__ __forceinline__ void cp_wait() {
    asm volatile("cp.async.wait_group %0;" :: "n"(N));
}

// ---------------------------------------------------------------------------
// fp16 SAGEConv: Out = act( agg @ Wl + X @ Wr + b ), mma m16n8k16 f16 -> f32.
// mode 0: store fp16 to Out (layer 1, with relu).
// mode 1: atomicAdd float2 of scale*(acc+bias) into Out (layer 2 fused combine).
// ---------------------------------------------------------------------------
#define A_STRIDE 40
#define A_BUF (128 * A_STRIDE)     // halves per buffer

__global__ void __launch_bounds__(256, 2)
conv_f16_kernel(const __half* __restrict__ Xh,    // fp16 x or h
                const __half* __restrict__ Aggh,  // fp16 agg
                const float* __restrict__ bl,
                void* __restrict__ Out,
                int layer, int relu, int mode) {
    __shared__ __half As[2 * A_BUF];
    __shared__ __half Ws[2 * A_BUF];

    const int g    = blockIdx.y;
    const int tid  = threadIdx.x;
    const int warp = tid >> 5;
    const int lane = tid & 31;
    const int wm   = warp >> 1;             // 0..3
    const int wn   = warp & 1;              // 0..1
    const int rowBase = blockIdx.x * 128;

    const __half* xg = Xh   + (size_t)g * N_NODES * D;
    const __half* ag = Aggh + (size_t)g * N_NODES * D;
    const __half* Wh = g_Wh + (size_t)(layer * 3 + g) * 32768;

    uint32_t As_base = (uint32_t)__cvta_generic_to_shared(As);
    uint32_t Ws_base = (uint32_t)__cvta_generic_to_shared(Ws);

    auto stageA = [&](int chunk, int buf) {
        #pragma unroll
        for (int i = 0; i < 2; ++i) {
            int idx = tid + i * 256;        // 0..511
            int r = idx >> 2, q = idx & 3;  // row, 16B-quarter (8 halves)
            int row = rowBase + r;
            const __half* src = ((chunk < 4) ? ag : xg)
                + (size_t)row * D + (chunk & 3) * 32 + q * 8;
            uint32_t dst = As_base + (uint32_t)((buf * A_BUF + r * A_STRIDE + q * 8) * 2);
            cp_async16z(dst, src, (row < N_NODES) ? 16 : 0);
        }
    };
    auto stageW = [&](int chunk, int buf) {
        const __half* src0 = Wh + (size_t)chunk * 4096;   // [n=128][kc=32]
        #pragma unroll
        for (int i = 0; i < 2; ++i) {
            int idx = tid + i * 256;
            int n = idx >> 2, q = idx & 3;
            uint32_t dst = Ws_base + (uint32_t)((buf * A_BUF + n * A_STRIDE + q * 8) * 2);
            cp_async16(dst, src0 + n * 32 + q * 8);
        }
    };

    float acc[2][8][4];
    #pragma unroll
    for (int mt = 0; mt < 2; ++mt)
        #pragma unroll
        for (int nt = 0; nt < 8; ++nt)
            #pragma unroll
            for (int i = 0; i < 4; ++i) acc[mt][nt][i] = 0.0f;

    stageA(0, 0); stageW(0, 0); cp_commit();

    #pragma unroll 1
    for (int c = 0; c < 8; ++c) {
        int buf = c & 1;
        if (c < 7) {
            stageA(c + 1, buf ^ 1); stageW(c + 1, buf ^ 1); cp_commit();
            cp_wait<1>();
        } else {
            cp_wait<0>();
        }
        __syncthreads();

        const __half* Ab = As + buf * A_BUF;
        const __half* Wb = Ws + buf * A_BUF;

        #pragma unroll
        for (int ks = 0; ks < 2; ++ks) {
            const int k0 = ks * 16;
            const int kc = k0 + (lane & 3) * 2;

            unsigned a[2][4];
            #pragma unroll
            for (int mt = 0; mt < 2; ++mt) {
                int ar = wm * 32 + mt * 16 + (lane >> 2);
                a[mt][0] = *(const unsigned*)&Ab[ar * A_STRIDE + kc];
                a[mt][1] = *(const unsigned*)&Ab[(ar + 8) * A_STRIDE + kc];
                a[mt][2] = *(const unsigned*)&Ab[ar * A_STRIDE + kc + 8];
                a[mt][3] = *(const unsigned*)&Ab[(ar + 8) * A_STRIDE + kc + 8];
            }

            #pragma unroll
            for (int nt = 0; nt < 8; ++nt) {
                int n0 = wn * 64 + nt * 8 + (lane >> 2);
                unsigned b0 = *(const unsigned*)&Wb[n0 * A_STRIDE + kc];
                unsigned b1 = *(const unsigned*)&Wb[n0 * A_STRIDE + kc + 8];
                #pragma unroll
                for (int mt = 0; mt < 2; ++mt) {
                    asm volatile(
                        "mma.sync.aligned.m16n8k16.row.col.f32.f16.f16.f32 "
                        "{%0,%1,%2,%3}, {%4,%5,%6,%7}, {%8,%9}, {%0,%1,%2,%3};"
                        : "+f"(acc[mt][nt][0]), "+f"(acc[mt][nt][1]),
                          "+f"(acc[mt][nt][2]), "+f"(acc[mt][nt][3])
                        : "r"(a[mt][0]), "r"(a[mt][1]), "r"(a[mt][2]), "r"(a[mt][3]),
                          "r"(b0), "r"(b1));
                }
            }
        }
        __syncthreads();
    }

    // Epilogue
    const float* bg = bl + (size_t)g * D;
    const float scale = (g == 0) ? 1.0f : 0.5f;

    #pragma unroll
    for (int mt = 0; mt < 2; ++mt) {
        const int r0 = rowBase + wm * 32 + mt * 16 + (lane >> 2);
        const int r1 = r0 + 8;
        #pragma unroll
        for (int nt = 0; nt < 8; ++nt) {
            const int ccol = wn * 64 + nt * 8 + (lane & 3) * 2;
            float2 b = *(const float2*)(bg + ccol);
            float2 o0 = make_float2(acc[mt][nt][0] + b.x, acc[mt][nt][1] + b.y);
            float2 o1 = make_float2(acc[mt][nt][2] + b.x, acc[mt][nt][3] + b.y);
            if (relu) {
                o0.x = fmaxf(o0.x, 0.f); o0.y = fmaxf(o0.y, 0.f);
                o1.x = fmaxf(o1.x, 0.f); o1.y = fmaxf(o1.y, 0.f);
            }
            if (mode == 0) {
                __half* og = (__half*)Out + (size_t)g * N_NODES * D;
                if (r0 < N_NODES) {
                    __half2 h = __floats2half2_rn(o0.x, o0.y);
                    *(__half2*)(og + (size_t)r0 * D + ccol) = h;
                }
                if (r1 < N_NODES) {
                    __half2 h = __floats2half2_rn(o1.x, o1.y);
                    *(__half2*)(og + (size_t)r1 * D + ccol) = h;
                }
            } else {
                // Fused combine: d_out += scale * (acc + bias)
                float* og = (float*)Out;
                if (r0 < N_NODES) {
                    float2 s = make_float2(o0.x * scale, o0.y * scale);
                    atomicAdd((float2*)(og + (size_t)r0 * D + ccol), s);
                }
                if (r1 < N_NODES) {
                    float2 s = make_float2(o1.x * scale, o1.y * scale);
                    atomicAdd((float2*)(og + (size_t)r1 * D + ccol), s);
                }
            }
        }
    }
}

extern "C" void kernel_launch(void* const* d_in, const int* in_sizes, int n_in,
                              void* d_out, int out_size) {
    const float* x   = (const float*)d_in[0];
    const void*  ei  = d_in[1];
    const float* Wl1 = (const float*)d_in[2];
    const float* bl1 = (const float*)d_in[3];
    const float* Wr1 = (const float*)d_in[4];
    const float* Wl2 = (const float*)d_in[5];
    const float* bl2 = (const float*)d_in[6];
    const float* Wr2 = (const float*)d_in[7];

    void *xh_p, *aggh_p, *h_p, *cnt_p;
    cudaGetSymbolAddress(&xh_p,   g_xh);
    cudaGetSymbolAddress(&aggh_p, g_aggh);
    cudaGetSymbolAddress(&h_p,    g_h);
    cudaGetSymbolAddress(&cnt_p,  g_cnt);
    __half* xh   = (__half*)xh_p;
    __half* aggh = (__half*)aggh_p;
    __half* h    = (__half*)h_p;

    // One-time side stream + fork/join events (host objects; per-call GPU work
    // is identical and deterministic; kernel_launch itself is not re-run during
    // graph replay).
    static cudaStream_t s2 = nullptr;
    static cudaEvent_t evFork = nullptr, evJoin = nullptr;
    if (!s2) {
        cudaStreamCreateWithFlags(&s2, cudaStreamNonBlocking);
        cudaEventCreateWithFlags(&evFork, cudaEventDisableTiming);
        cudaEventCreateWithFlags(&evJoin, cudaEventDisableTiming);
    }

    // ---- fork: preconverts + output zero on s2, CSR build on main ----
    cudaEventRecord(evFork, 0);
    cudaStreamWaitEvent(s2, evFork, 0);

    // s2 branch: weight/x preconverts + d_out zero (independent of CSR)
    wconv_kernel<<<(2 * 3 * 32768) / 256, 256, 0, s2>>>(Wl1, Wr1, Wl2, Wr2);
    const long long nv4 = (long long)NTOT * D / 4;
    xh_kernel<<<(unsigned)((nv4 + 255) / 256), 256, 0, s2>>>(x);
    cudaMemsetAsync(d_out, 0, (size_t)out_size * sizeof(float), s2);
    cudaEventRecord(evJoin, s2);

    // main branch: dtype detect + CSR build
    detect_idx_kernel<<<1, 32>>>((const int*)ei);
    cudaMemsetAsync(cnt_p, 0, sizeof(g_cnt));
    const int eblk = 256;
    const int egrid = (EQTOT + eblk - 1) / eblk;
    count_kernel<<<egrid, eblk>>>(ei);
    scan1_kernel<<<SCAN_NB, SCAN_BLK>>>();
    scan2_kernel<<<1, 512>>>();
    scan3_kernel<<<SCAN_NB, SCAN_BLK>>>();
    fill_kernel<<<egrid, eblk>>>(ei);

    // join before the gather/conv chain (needs xh, Wh, d_out zeroed, CSR)
    cudaStreamWaitEvent(0, evJoin, 0);

    // 2) layer-1 aggregation (fp16 xh in, fp16 agg out)
    const int ggrid = (NTOT * 32 + 255) / 256;
    gather_f16_kernel<<<ggrid, 256>>>(xh, aggh);

    // 3) layer-1 conv + relu -> h (fp16)
    dim3 cgrid((N_NODES + 127) / 128, 3);
    conv_f16_kernel<<<cgrid, 256>>>(xh, aggh, bl1, h, 0, 1, 0);

    // 4) layer-2 aggregation (fp16 h in, fp16 agg out)
    gather_f16_kernel<<<ggrid, 256>>>(h, aggh);

    // 5) layer-2 conv -> fused combine into d_out (atomic, scaled)
    conv_f16_kernel<<<cgrid, 256>>>(h, aggh, bl2, d_out, 1, 0, 1);
}

// round 17
// speedup vs baseline: 1.3884x; 1.3884x over previous
#include <cuda_runtime.h>
#include <cuda_fp16.h>
#include <cstdint>

#define N_NODES 100000
#define N_EDGES 800000
#define D 128
#define NTOT (3 * N_NODES)
#define ETOT (3 * N_EDGES)
#define EQTOT (ETOT / 4)
#define EQ_PER_G (N_EDGES / 4)
#define SCAN_BLK 1024
#define SCAN_NB ((NTOT + SCAN_BLK - 1) / SCAN_BLK)   // 293
#define NTILES ((N_NODES + 127) / 128)               // 782
#define CONV_GRID_X 49                                // 49*16 >= 782, 147 blocks

// Scratch (device globals — allocation-free rule)
__device__ __half g_xh[3 * N_NODES * D];    // x in fp16
__device__ __half g_aggh[3 * N_NODES * D];  // mean-aggregated messages, fp16
__device__ __half g_h[3 * N_NODES * D];     // layer-1 activations, fp16
__device__ int    g_is64;
// fp16 weights, linear: [layer*3+g][n=128][k=256]
__device__ __half g_Wh[2 * 3 * 128 * 256];

// CSR scratch
__device__ int g_cnt[NTOT];
__device__ int g_rowptr[NTOT + 1];
__device__ int g_cursor[NTOT];
__device__ int g_col[ETOT];
__device__ int g_bsum[SCAN_NB];

// ---------------------------------------------------------------------------
__global__ void detect_idx_kernel(const int* __restrict__ ei_words) {
    if (threadIdx.x == 0 && blockIdx.x == 0) {
        int bad = 0;
        #pragma unroll
        for (int i = 0; i < 64; ++i) bad |= ei_words[2 * i + 1];
        g_is64 = (bad == 0) ? 1 : 0;
    }
}

// ---------------------------------------------------------------------------
// CSR build: count -> scan -> fill.  4 edges per thread.
// ---------------------------------------------------------------------------
__device__ __forceinline__ void load_dst4(const void* ei_raw, int g, int e4, int* d) {
    if (g_is64) {
        const long long* ei = (const long long*)ei_raw
            + (long long)g * 2 * N_EDGES + N_EDGES + e4;
        longlong2 a = *(const longlong2*)ei;
        longlong2 b = *(const longlong2*)(ei + 2);
        d[0] = (int)a.x; d[1] = (int)a.y; d[2] = (int)b.x; d[3] = (int)b.y;
    } else {
        const int* ei = (const int*)ei_raw
            + (long long)g * 2 * N_EDGES + N_EDGES + e4;
        int4 v = *(const int4*)ei;
        d[0] = v.x; d[1] = v.y; d[2] = v.z; d[3] = v.w;
    }
}

__device__ __forceinline__ void load_src4(const void* ei_raw, int g, int e4, int* s) {
    if (g_is64) {
        const long long* ei = (const long long*)ei_raw
            + (long long)g * 2 * N_EDGES + e4;
        longlong2 a = *(const longlong2*)ei;
        longlong2 b = *(const longlong2*)(ei + 2);
        s[0] = (int)a.x; s[1] = (int)a.y; s[2] = (int)b.x; s[3] = (int)b.y;
    } else {
        const int* ei = (const int*)ei_raw
            + (long long)g * 2 * N_EDGES + e4;
        int4 v = *(const int4*)ei;
        s[0] = v.x; s[1] = v.y; s[2] = v.z; s[3] = v.w;
    }
}

__global__ void count_kernel(const void* __restrict__ ei_raw) {
    int i = blockIdx.x * blockDim.x + threadIdx.x;
    if (i >= EQTOT) return;
    int g  = i / EQ_PER_G;
    int e4 = (i - g * EQ_PER_G) * 4;
    int d[4];
    load_dst4(ei_raw, g, e4, d);
    #pragma unroll
    for (int j = 0; j < 4; ++j)
        atomicAdd(&g_cnt[g * N_NODES + d[j]], 1);
}

__global__ void scan1_kernel() {
    __shared__ int s[SCAN_BLK];
    int idx = blockIdx.x * SCAN_BLK + threadIdx.x;
    int v = (idx < NTOT) ? g_cnt[idx] : 0;
    s[threadIdx.x] = v;
    __syncthreads();
    #pragma unroll
    for (int off = 1; off < SCAN_BLK; off <<= 1) {
        int t = (threadIdx.x >= off) ? s[threadIdx.x - off] : 0;
        __syncthreads();
        s[threadIdx.x] += t;
        __syncthreads();
    }
    if (idx < NTOT) g_rowptr[idx] = s[threadIdx.x] - v;
    if (threadIdx.x == SCAN_BLK - 1) g_bsum[blockIdx.x] = s[SCAN_BLK - 1];
}

__global__ void scan2_kernel() {
    __shared__ int s[512];
    int v = (threadIdx.x < SCAN_NB) ? g_bsum[threadIdx.x] : 0;
    s[threadIdx.x] = v;
    __syncthreads();
    #pragma unroll
    for (int off = 1; off < 512; off <<= 1) {
        int t = (threadIdx.x >= off) ? s[threadIdx.x - off] : 0;
        __syncthreads();
        s[threadIdx.x] += t;
        __syncthreads();
    }
    if (threadIdx.x < SCAN_NB) g_bsum[threadIdx.x] = s[threadIdx.x] - v;
}

__global__ void scan3_kernel() {
    int idx = blockIdx.x * SCAN_BLK + threadIdx.x;
    if (idx < NTOT) {
        int r = g_rowptr[idx] + g_bsum[blockIdx.x];
        g_rowptr[idx] = r;
        g_cursor[idx] = r;
    }
    if (idx == 0) g_rowptr[NTOT] = ETOT;
}

__global__ void fill_kernel(const void* __restrict__ ei_raw) {
    int i = blockIdx.x * blockDim.x + threadIdx.x;
    if (i >= EQTOT) return;
    int g  = i / EQ_PER_G;
    int e4 = (i - g * EQ_PER_G) * 4;
    int s[4], d[4];
    load_src4(ei_raw, g, e4, s);
    load_dst4(ei_raw, g, e4, d);
    #pragma unroll
    for (int j = 0; j < 4; ++j) {
        int pos = atomicAdd(&g_cursor[g * N_NODES + d[j]], 1);
        g_col[pos] = s[j];
    }
}

// ---------------------------------------------------------------------------
// x -> fp16 preconvert
// ---------------------------------------------------------------------------
__global__ void xh_kernel(const float* __restrict__ X) {
    long long i = (long long)blockIdx.x * blockDim.x + threadIdx.x;
    const long long nv = (long long)NTOT * D / 4;
    if (i >= nv) return;
    float4 v = ((const float4*)X)[i];
    __half2 h0 = __floats2half2_rn(v.x, v.y);
    __half2 h1 = __floats2half2_rn(v.z, v.w);
    uint2 o;
    o.x = *(unsigned*)&h0;
    o.y = *(unsigned*)&h1;
    ((uint2*)g_xh)[i] = o;
}

// Weight preconvert: g_Wh[(lg*128 + n)*256 + k] = fp16(W[k][n]); k<128 Wl, else Wr
__global__ void wconv_kernel(const float* __restrict__ Wl1, const float* __restrict__ Wr1,
                             const float* __restrict__ Wl2, const float* __restrict__ Wr2) {
    int i = blockIdx.x * blockDim.x + threadIdx.x;   // < 2*3*128*256 = 196608
    int lg  = i >> 15;            // layer*3+g
    int rem = i & 32767;
    int n   = rem >> 8;           // 0..127
    int k   = rem & 255;          // 0..255
    int layer = lg / 3, g = lg % 3;
    const float* Wl = layer ? Wl2 : Wl1;
    const float* Wr = layer ? Wr2 : Wr1;
    float v = (k < 128) ? Wl[(g * 128 + k) * 128 + n]
                        : Wr[(g * 128 + (k - 128)) * 128 + n];
    g_Wh[i] = __float2half_rn(v);
}

// ---------------------------------------------------------------------------
// Gather aggregation (CSR, no atomics). fp16 input -> fp16 agg (both layers).
// ---------------------------------------------------------------------------
__global__ void __launch_bounds__(256)
gather_f16_kernel(const __half* __restrict__ X, __half* __restrict__ agg) {
    int widx = blockIdx.x * (blockDim.x >> 5) + (threadIdx.x >> 5);
    int lane = threadIdx.x & 31;
    if (widx >= NTOT) return;

    int g = widx / N_NODES;
    const uint2* xg = (const uint2*)(X + (size_t)g * N_NODES * D);

    int start = g_rowptr[widx];
    int end   = g_rowptr[widx + 1];

    float4 acc0 = make_float4(0.f, 0.f, 0.f, 0.f);
    float4 acc1 = make_float4(0.f, 0.f, 0.f, 0.f);
    int p = start;
    for (; p + 1 < end; p += 2) {
        int s0 = g_col[p], s1 = g_col[p + 1];
        uint2 v0 = xg[(size_t)s0 * 32 + lane];
        uint2 v1 = xg[(size_t)s1 * 32 + lane];
        float2 f0 = __half22float2(*(__half2*)&v0.x);
        float2 f1 = __half22float2(*(__half2*)&v0.y);
        acc0.x += f0.x; acc0.y += f0.y; acc0.z += f1.x; acc0.w += f1.y;
        float2 f2 = __half22float2(*(__half2*)&v1.x);
        float2 f3 = __half22float2(*(__half2*)&v1.y);
        acc1.x += f2.x; acc1.y += f2.y; acc1.z += f3.x; acc1.w += f3.y;
    }
    if (p < end) {
        int s0 = g_col[p];
        uint2 v0 = xg[(size_t)s0 * 32 + lane];
        float2 f0 = __half22float2(*(__half2*)&v0.x);
        float2 f1 = __half22float2(*(__half2*)&v0.y);
        acc0.x += f0.x; acc0.y += f0.y; acc0.z += f1.x; acc0.w += f1.y;
    }
    acc0.x += acc1.x; acc0.y += acc1.y; acc0.z += acc1.z; acc0.w += acc1.w;

    int deg = end - start;
    float norm = 1.0f / (float)max(deg, 1);
    __half2 h0 = __floats2half2_rn(acc0.x * norm, acc0.y * norm);
    __half2 h1 = __floats2half2_rn(acc0.z * norm, acc0.w * norm);
    uint2 o;
    o.x = *(unsigned*)&h0;
    o.y = *(unsigned*)&h1;
    ((uint2*)agg)[(size_t)widx * 32 + lane] = o;
}

// ---------------------------------------------------------------------------
// cp.async helpers
// ---------------------------------------------------------------------------
__device__ __forceinline__ void cp_async16z(uint32_t dst, const void* src, int bytes) {
    asm volatile("cp.async.cg.shared.global [%0], [%1], 16, %2;"
                 :: "r"(dst), "l"(src), "r"(bytes));
}
__device__ __forceinline__ void cp_async16(uint32_t dst, const void* src) {
    asm volatile("cp.async.cg.shared.global [%0], [%1], 16;"
                 :: "r"(dst), "l"(src));
}
__device__ __forceinline__ void cp_commit() {
    asm volatile("cp.async.commit_group;");
}
template <int N>
__device__ __forceinline__ void cp_wait() {
    asm volatile("cp.async.wait_group %0;" :: "n"(N));
}

// ---------------------------------------------------------------------------
// Persistent-tile fp16 SAGEConv.
// Block: 256 threads, 1 block/SM (203 KB smem). Each block: fixed graph g,
// W resident in smem; loops over row tiles (stride CONV_GRID_X); whole 128x256
// A panel double-buffered via cp.async across tiles. 2 syncs per tile.
// mode 0: fp16 store + relu (layer 1). mode 1: scaled float2 atomicAdd (layer 2).
// ---------------------------------------------------------------------------
#define TK 264                          // halves per smem row (256 + 8 pad)
#define PANEL_HALVES (128 * TK)         // 33792 halves = 67584 B
#define CONV_SMEM_BYTES (3 * PANEL_HALVES * 2)   // A0, A1, W = 202752 B

__global__ void __launch_bounds__(256, 1)
conv_f16_kernel(const __half* __restrict__ Xh,    // fp16 x or h
                const __half* __restrict__ Aggh,  // fp16 agg
                const float* __restrict__ bl,
                void* __restrict__ Out,
                int layer, int relu, int mode) {
    extern __shared__ __half smem[];
    __half* Abuf[2] = { smem, smem + PANEL_HALVES };
    __half* Wbuf    = smem + 2 * PANEL_HALVES;

    const int g    = blockIdx.y;
    const int tid  = threadIdx.x;
    const int warp = tid >> 5;
    const int lane = tid & 31;
    const int wm   = warp >> 1;             // 0..3
    const int wn   = warp & 1;              // 0..1

    const __half* xg = Xh   + (size_t)g * N_NODES * D;
    const __half* ag = Aggh + (size_t)g * N_NODES * D;
    const __half* Wg = g_Wh + (size_t)(layer * 3 + g) * 128 * 256;
    const float*  bg = bl + (size_t)g * D;
    const float scale = (g == 0) ? 1.0f : 0.5f;

    uint32_t smem_base = (uint32_t)__cvta_generic_to_shared(smem);
    uint32_t A_base[2] = { smem_base, smem_base + PANEL_HALVES * 2 };
    uint32_t W_base    = smem_base + 2 * PANEL_HALVES * 2;

    // Stage full A panel for a tile: 128 rows x 256 halves (4096 x 16B).
    // Row layout: [agg row (128h) | x row (128h)], smem row stride TK halves.
    auto stageA = [&](int tile, int bi) {
        const int rowBase = tile * 128;
        #pragma unroll
        for (int i = 0; i < 16; ++i) {
            int idx = tid + i * 256;        // 0..4095
            int r = idx >> 5, q = idx & 31; // row, 16B-chunk (8 halves)
            int row = rowBase + r;
            int bytes = (row < N_NODES) ? 16 : 0;
            if (row >= N_NODES) row = N_NODES - 1;   // safe address
            const __half* src = (q < 16)
                ? (ag + (size_t)row * D + q * 8)
                : (xg + (size_t)row * D + (q - 16) * 8);
            uint32_t dst = A_base[bi] + (uint32_t)((r * TK + q * 8) * 2);
            cp_async16z(dst, src, bytes);
        }
    };
    // Stage W once: 128 n-rows x 256 k halves.
    auto stageW = [&]() {
        #pragma unroll
        for (int i = 0; i < 16; ++i) {
            int idx = tid + i * 256;
            int n = idx >> 5, q = idx & 31;
            uint32_t dst = W_base + (uint32_t)((n * TK + q * 8) * 2);
            cp_async16(dst, Wg + (size_t)n * 256 + q * 8);
        }
    };

    int t = blockIdx.x;
    stageW();
    if (t < NTILES) stageA(t, 0);
    cp_commit();

    int bi = 0;
    for (; t < NTILES; t += CONV_GRID_X) {
        int tn = t + CONV_GRID_X;
        if (tn < NTILES) {
            stageA(tn, bi ^ 1); cp_commit();
            cp_wait<1>();
        } else {
            cp_wait<0>();
        }
        __syncthreads();

        const __half* Ab = Abuf[bi];

        float acc[2][8][4];
        #pragma unroll
        for (int mt = 0; mt < 2; ++mt)
            #pragma unroll
            for (int nt = 0; nt < 8; ++nt)
                #pragma unroll
                for (int i = 0; i < 4; ++i) acc[mt][nt][i] = 0.0f;

        #pragma unroll 4
        for (int ks = 0; ks < 16; ++ks) {
            const int kc = ks * 16 + (lane & 3) * 2;

            unsigned a[2][4];
            #pragma unroll
            for (int mt = 0; mt < 2; ++mt) {
                int ar = wm * 32 + mt * 16 + (lane >> 2);
                a[mt][0] = *(const unsigned*)&Ab[ar * TK + kc];
                a[mt][1] = *(const unsigned*)&Ab[(ar + 8) * TK + kc];
                a[mt][2] = *(const unsigned*)&Ab[ar * TK + kc + 8];
                a[mt][3] = *(const unsigned*)&Ab[(ar + 8) * TK + kc + 8];
            }

            #pragma unroll
            for (int nt = 0; nt < 8; ++nt) {
                int n0 = wn * 64 + nt * 8 + (lane >> 2);
                unsigned b0 = *(const unsigned*)&Wbuf[n0 * TK + kc];
                unsigned b1 = *(const unsigned*)&Wbuf[n0 * TK + kc + 8];
                #pragma unroll
                for (int mt = 0; mt < 2; ++mt) {
                    asm volatile(
                        "mma.sync.aligned.m16n8k16.row.col.f32.f16.f16.f32 "
                        "{%0,%1,%2,%3}, {%4,%5,%6,%7}, {%8,%9}, {%0,%1,%2,%3};"
                        : "+f"(acc[mt][nt][0]), "+f"(acc[mt][nt][1]),
                          "+f"(acc[mt][nt][2]), "+f"(acc[mt][nt][3])
                        : "r"(a[mt][0]), "r"(a[mt][1]), "r"(a[mt][2]), "r"(a[mt][3]),
                          "r"(b0), "r"(b1));
                }
            }
        }

        // Epilogue for tile t
        const int rowBase = t * 128;
        #pragma unroll
        for (int mt = 0; mt < 2; ++mt) {
            const int r0 = rowBase + wm * 32 + mt * 16 + (lane >> 2);
            const int r1 = r0 + 8;
            #pragma unroll
            for (int nt = 0; nt < 8; ++nt) {
                const int ccol = wn * 64 + nt * 8 + (lane & 3) * 2;
                float2 b = *(const float2*)(bg + ccol);
                float2 o0 = make_float2(acc[mt][nt][0] + b.x, acc[mt][nt][1] + b.y);
                float2 o1 = make_float2(acc[mt][nt][2] + b.x, acc[mt][nt][3] + b.y);
                if (relu) {
                    o0.x = fmaxf(o0.x, 0.f); o0.y = fmaxf(o0.y, 0.f);
                    o1.x = fmaxf(o1.x, 0.f); o1.y = fmaxf(o1.y, 0.f);
                }
                if (mode == 0) {
                    __half* og = (__half*)Out + (size_t)g * N_NODES * D;
                    if (r0 < N_NODES) {
                        __half2 h = __floats2half2_rn(o0.x, o0.y);
                        *(__half2*)(og + (size_t)r0 * D + ccol) = h;
                    }
                    if (r1 < N_NODES) {
                        __half2 h = __floats2half2_rn(o1.x, o1.y);
                        *(__half2*)(og + (size_t)r1 * D + ccol) = h;
                    }
                } else {
                    float* og = (float*)Out;
                    if (r0 < N_NODES) {
                        float2 s = make_float2(o0.x * scale, o0.y * scale);
                        atomicAdd((float2*)(og + (size_t)r0 * D + ccol), s);
                    }
                    if (r1 < N_NODES) {
                        float2 s = make_float2(o1.x * scale, o1.y * scale);
                        atomicAdd((float2*)(og + (size_t)r1 * D + ccol), s);
                    }
                }
            }
        }
        __syncthreads();   // buffer bi free for restaging next iteration
        bi ^= 1;
    }
}

extern "C" void kernel_launch(void* const* d_in, const int* in_sizes, int n_in,
                              void* d_out, int out_size) {
    const float* x   = (const float*)d_in[0];
    const void*  ei  = d_in[1];
    const float* Wl1 = (const float*)d_in[2];
    const float* bl1 = (const float*)d_in[3];
    const float* Wr1 = (const float*)d_in[4];
    const float* Wl2 = (const float*)d_in[5];
    const float* bl2 = (const float*)d_in[6];
    const float* Wr2 = (const float*)d_in[7];

    void *xh_p, *aggh_p, *h_p, *cnt_p;
    cudaGetSymbolAddress(&xh_p,   g_xh);
    cudaGetSymbolAddress(&aggh_p, g_aggh);
    cudaGetSymbolAddress(&h_p,    g_h);
    cudaGetSymbolAddress(&cnt_p,  g_cnt);
    __half* xh   = (__half*)xh_p;
    __half* aggh = (__half*)aggh_p;
    __half* h    = (__half*)h_p;

    cudaFuncSetAttribute(conv_f16_kernel,
                         cudaFuncAttributeMaxDynamicSharedMemorySize,
                         CONV_SMEM_BYTES);

    // 0) dtype detect + preconverts + output zero (single stream)
    detect_idx_kernel<<<1, 32>>>((const int*)ei);
    wconv_kernel<<<(2 * 3 * 128 * 256) / 256, 256>>>(Wl1, Wr1, Wl2, Wr2);
    const long long nv4 = (long long)NTOT * D / 4;
    xh_kernel<<<(unsigned)((nv4 + 255) / 256), 256>>>(x);
    cudaMemsetAsync(d_out, 0, (size_t)out_size * sizeof(float));

    // 1) CSR build (shared by both layers), 4 edges/thread
    cudaMemsetAsync(cnt_p, 0, sizeof(g_cnt));
    const int eblk = 256;
    const int egrid = (EQTOT + eblk - 1) / eblk;
    count_kernel<<<egrid, eblk>>>(ei);
    scan1_kernel<<<SCAN_NB, SCAN_BLK>>>();
    scan2_kernel<<<1, 512>>>();
    scan3_kernel<<<SCAN_NB, SCAN_BLK>>>();
    fill_kernel<<<egrid, eblk>>>(ei);

    // 2) layer-1 aggregation (fp16 xh in, fp16 agg out)
    const int ggrid = (NTOT * 32 + 255) / 256;
    gather_f16_kernel<<<ggrid, 256>>>(xh, aggh);

    // 3) layer-1 conv + relu -> h (fp16), persistent tiles
    dim3 cgrid(CONV_GRID_X, 3);
    conv_f16_kernel<<<cgrid, 256, CONV_SMEM_BYTES>>>(xh, aggh, bl1, h, 0, 1, 0);

    // 4) layer-2 aggregation (fp16 h in, fp16 agg out)
    gather_f16_kernel<<<ggrid, 256>>>(h, aggh);

    // 5) layer-2 conv -> fused combine into d_out (atomic, scaled)
    conv_f16_kernel<<<cgrid, 256, CONV_SMEM_BYTES>>>(h, aggh, bl2, d_out, 1, 0, 1);
}